// round 1
// baseline (speedup 1.0000x reference)
#include <cuda_runtime.h>

#define BATCH 32
#define SEQ   512
#define DIMK  64
#define NDIAG 1023          // 2*SEQ - 1
#define DPITCH 1024         // padded diagonal pitch
#define BIGF  1e30f

// Diagonal-major distance scratch: Ddiag[b][p][i] = D[b, i, p-i]  (64 MB, lives in L2)
__device__ float g_Ddiag[BATCH * DPITCH * SEQ];

// ---------------------------------------------------------------------------
// Phase 1: D = x2 + y2 - 2 x.y, written diagonal-major with coalesced stores.
// Block = 128 threads, computes a 128(i) x 128(j) tile for one batch.
// Thread t owns row i = i0 + t; x row lives in registers; Y tile transposed
// in smem so the inner loop is broadcast-LDS + FFMA.
// ---------------------------------------------------------------------------
#define TI 128
#define TJ 128
#define YS_STRIDE 132   // (4k + j) mod 32 -> conflict-free-ish, 16B aligned rows
#define DST_STRIDE 9

__global__ __launch_bounds__(128) void gemm_diag_kernel(
    const float* __restrict__ X, const float* __restrict__ Y) {
  const int t  = threadIdx.x;
  const int i0 = blockIdx.x * TI;
  const int j0 = blockIdx.y * TJ;
  const int b  = blockIdx.z;

  __shared__ float Ys[DIMK * YS_STRIDE];  // [k][j]
  __shared__ float y2s[TJ];
  __shared__ float Dst[TI * DST_STRIDE];  // staging for one 128x8 j-block

  const float* Xb = X + ((size_t)b * SEQ + i0) * DIMK;
  const float* Yb = Y + ((size_t)b * SEQ + j0) * DIMK;

  // Load Y tile transposed into smem (coalesced global reads).
  for (int e = t; e < TJ * DIMK; e += 128) {
    int j = e >> 6;      // DIMK = 64
    int k = e & 63;
    Ys[k * YS_STRIDE + j] = Yb[e];
  }

  // X row -> registers, plus x2.
  float xr[DIMK];
  float x2 = 0.f;
#pragma unroll
  for (int k4 = 0; k4 < DIMK; k4 += 4) {
    float4 v = *reinterpret_cast<const float4*>(Xb + (size_t)t * DIMK + k4);
    xr[k4] = v.x; xr[k4 + 1] = v.y; xr[k4 + 2] = v.z; xr[k4 + 3] = v.w;
  }
#pragma unroll
  for (int k = 0; k < DIMK; k++) x2 += xr[k] * xr[k];

  __syncthreads();

  // y2 per column (thread t handles column t).
  {
    float a = 0.f;
#pragma unroll
    for (int k = 0; k < DIMK; k++) {
      float yv = Ys[k * YS_STRIDE + t];
      a += yv * yv;
    }
    y2s[t] = a;
  }
  __syncthreads();

  float* gout = g_Ddiag + (size_t)b * (DPITCH * SEQ);
  const int w = t >> 5, lane = t & 31;

  for (int jb = 0; jb < TJ / 8; jb++) {
    float acc[8];
#pragma unroll
    for (int m = 0; m < 8; m++) acc[m] = 0.f;

#pragma unroll
    for (int k = 0; k < DIMK; k++) {
      const float4 ya = *reinterpret_cast<const float4*>(&Ys[k * YS_STRIDE + jb * 8]);
      const float4 yb = *reinterpret_cast<const float4*>(&Ys[k * YS_STRIDE + jb * 8 + 4]);
      const float xv = xr[k];
      acc[0] += xv * ya.x; acc[1] += xv * ya.y;
      acc[2] += xv * ya.z; acc[3] += xv * ya.w;
      acc[4] += xv * yb.x; acc[5] += xv * yb.y;
      acc[6] += xv * yb.z; acc[7] += xv * yb.w;
    }

#pragma unroll
    for (int m = 0; m < 8; m++) {
      Dst[t * DST_STRIDE + m] = x2 + y2s[jb * 8 + m] - 2.f * acc[m];
    }
    __syncthreads();

    // Write the 128x8 sub-tile out along global anti-diagonals (coalesced).
    // Sub-tile diagonals d = 0..134; each warp iteration covers 4 diagonals
    // with 8 lanes each.
    const int p0 = i0 + j0 + jb * 8;
    for (int dbase = w * 4; dbase < TI + 8 - 1; dbase += 16) {
      int d = dbase + (lane >> 3);
      int q = lane & 7;
      if (d < TI + 8 - 1) {
        int lo = d - 7 < 0 ? 0 : d - 7;
        int hi = d < TI - 1 ? d : TI - 1;
        int irow = lo + q;
        if (irow <= hi) {
          gout[(size_t)(p0 + d) * SEQ + (i0 + irow)] =
              Dst[irow * DST_STRIDE + (d - irow)];
        }
      }
    }
    __syncthreads();
  }
}

// ---------------------------------------------------------------------------
// Phase 2: anti-diagonal wavefront soft-DTW DP. One CTA per batch,
// thread i = row i. Registers v1 (diag p-1) / v2 (diag p-2); neighbors via
// shfl_up; warp-boundary values via parity-double-buffered smem mailboxes
// (one __syncthreads per diagonal).
// ---------------------------------------------------------------------------
__global__ __launch_bounds__(512) void softdtw_dp_kernel(float* __restrict__ out) {
  const int b = blockIdx.x;
  const int i = threadIdx.x;
  const int lane = i & 31, w = i >> 5;

  __shared__ float sb1[2][16];
  __shared__ float sb2[2][16];
  if (i < 16) {
    sb1[0][i] = BIGF; sb1[1][i] = BIGF;
    sb2[0][i] = BIGF; sb2[1][i] = BIGF;
  }

  float v1 = BIGF, v2 = BIGF;
  const float* dp = g_Ddiag + (size_t)b * (DPITCH * SEQ) + i;
  __syncthreads();

  for (int p = 0; p < NDIAG; ++p) {
    const int rs = p & 1;
    float nb1 = __shfl_up_sync(0xffffffffu, v1, 1);
    float nb2 = __shfl_up_sync(0xffffffffu, v2, 1);
    if (lane == 0) {
      nb1 = (w == 0) ? BIGF : sb1[rs][w - 1];
      nb2 = (w == 0) ? ((p == 0) ? 0.0f : BIGF) : sb2[rs][w - 1];
    }
    const float dd = nb2;      // R[i-1][j-1]  (diag p-2)
    const float up = nb1;      // R[i-1][j]    (diag p-1)
    const float lf = v1;       // R[i][j-1]    (diag p-1)

    // softmin with min-shift; BIG arithmetic is exact in fp32 (no NaN).
    float m = fminf(fminf(dd, up), lf);
    float e = __expf(m - dd) + __expf(m - up) + __expf(m - lf);
    float sm = m - __logf(e);

    float g = dp[(size_t)p * SEQ];              // coalesced; always in-bounds
    unsigned jj = (unsigned)(p - i);
    float nv = (jj < (unsigned)SEQ) ? (g + sm) : BIGF;

    v2 = v1;
    v1 = nv;
    if (lane == 31) {           // publish boundary for warp w+1's next step
      sb1[rs ^ 1][w] = v1;
      sb2[rs ^ 1][w] = v2;
    }
    __syncthreads();
  }

  if (i == SEQ - 1) out[b] = v1;   // R[N, M]
}

// ---------------------------------------------------------------------------
extern "C" void kernel_launch(void* const* d_in, const int* in_sizes, int n_in,
                              void* d_out, int out_size) {
  const float* X = (const float*)d_in[0];
  const float* Y = (const float*)d_in[1];
  float* out = (float*)d_out;

  dim3 grid_g(SEQ / TI, SEQ / TJ, BATCH);
  gemm_diag_kernel<<<grid_g, 128>>>(X, Y);
  softdtw_dp_kernel<<<BATCH, SEQ>>>(out);
}

// round 2
// speedup vs baseline: 1.9142x; 1.9142x over previous
#include <cuda_runtime.h>

#define BATCH 32
#define SEQ   512
#define DIMK  64
#define NDIAG 1023          // 2*SEQ - 1
#define DPITCH 1024         // padded diagonal pitch (>= NDIAG+1 for prefetch overrun)
#define BIGF  1e30f
#define L2E   1.4426950408889634f
#define LN2   0.6931471805599453f

// Diagonal-major distance scratch: Ddiag[b][p][i] = D[b, i, p-i]  (64 MB)
__device__ float g_Ddiag[BATCH * DPITCH * SEQ];

// ---------------------------------------------------------------------------
// Phase 1: D = x2 + y2 - 2 x.y, written diagonal-major with coalesced stores.
// ---------------------------------------------------------------------------
#define TI 128
#define TJ 128
#define YS_STRIDE 132
#define DST_STRIDE 9

__global__ __launch_bounds__(128) void gemm_diag_kernel(
    const float* __restrict__ X, const float* __restrict__ Y) {
  const int t  = threadIdx.x;
  const int i0 = blockIdx.x * TI;
  const int j0 = blockIdx.y * TJ;
  const int b  = blockIdx.z;

  __shared__ float Ys[DIMK * YS_STRIDE];  // [k][j]
  __shared__ float y2s[TJ];
  __shared__ float Dst[TI * DST_STRIDE];  // staging for one 128x8 j-block

  const float* Xb = X + ((size_t)b * SEQ + i0) * DIMK;
  const float* Yb = Y + ((size_t)b * SEQ + j0) * DIMK;

  for (int e = t; e < TJ * DIMK; e += 128) {
    int j = e >> 6;
    int k = e & 63;
    Ys[k * YS_STRIDE + j] = Yb[e];
  }

  float xr[DIMK];
  float x2 = 0.f;
#pragma unroll
  for (int k4 = 0; k4 < DIMK; k4 += 4) {
    float4 v = *reinterpret_cast<const float4*>(Xb + (size_t)t * DIMK + k4);
    xr[k4] = v.x; xr[k4 + 1] = v.y; xr[k4 + 2] = v.z; xr[k4 + 3] = v.w;
  }
#pragma unroll
  for (int k = 0; k < DIMK; k++) x2 += xr[k] * xr[k];

  __syncthreads();

  {
    float a = 0.f;
#pragma unroll
    for (int k = 0; k < DIMK; k++) {
      float yv = Ys[k * YS_STRIDE + t];
      a += yv * yv;
    }
    y2s[t] = a;
  }
  __syncthreads();

  float* gout = g_Ddiag + (size_t)b * (DPITCH * SEQ);
  const int w = t >> 5, lane = t & 31;

  for (int jb = 0; jb < TJ / 8; jb++) {
    float acc[8];
#pragma unroll
    for (int m = 0; m < 8; m++) acc[m] = 0.f;

#pragma unroll
    for (int k = 0; k < DIMK; k++) {
      const float4 ya = *reinterpret_cast<const float4*>(&Ys[k * YS_STRIDE + jb * 8]);
      const float4 yb = *reinterpret_cast<const float4*>(&Ys[k * YS_STRIDE + jb * 8 + 4]);
      const float xv = xr[k];
      acc[0] += xv * ya.x; acc[1] += xv * ya.y;
      acc[2] += xv * ya.z; acc[3] += xv * ya.w;
      acc[4] += xv * yb.x; acc[5] += xv * yb.y;
      acc[6] += xv * yb.z; acc[7] += xv * yb.w;
    }

#pragma unroll
    for (int m = 0; m < 8; m++) {
      Dst[t * DST_STRIDE + m] = x2 + y2s[jb * 8 + m] - 2.f * acc[m];
    }
    __syncthreads();

    const int p0 = i0 + j0 + jb * 8;
    for (int dbase = w * 4; dbase < TI + 8 - 1; dbase += 16) {
      int d = dbase + (lane >> 3);
      int q = lane & 7;
      if (d < TI + 8 - 1) {
        int lo = d - 7 < 0 ? 0 : d - 7;
        int hi = d < TI - 1 ? d : TI - 1;
        int irow = lo + q;
        if (irow <= hi) {
          gout[(size_t)(p0 + d) * SEQ + (i0 + irow)] =
              Dst[irow * DST_STRIDE + (d - irow)];
        }
      }
    }
    __syncthreads();
  }
}

// ---------------------------------------------------------------------------
// Phase 2: wavefront DP. 128 threads (4 warps), 4 rows per thread.
// State held in base-2-scaled domain (R' = R * log2e); D scaled at consumption
// via one FMA; result scaled back by ln2.
// ---------------------------------------------------------------------------
__device__ __forceinline__ float ex2(float x) {
  float r; asm("ex2.approx.f32 %0, %1;" : "=f"(r) : "f"(x)); return r;
}
__device__ __forceinline__ float lg2(float x) {
  float r; asm("lg2.approx.f32 %0, %1;" : "=f"(r) : "f"(x)); return r;
}

// softmin (scaled domain) of 3 values using exact min/median/max; 2 EX2 + 1 LG2.
__device__ __forceinline__ float softmin3s(float a, float b, float c) {
  float u = fminf(a, b), v = fmaxf(a, b);
  float mn = fminf(u, c);
  float mx = fmaxf(v, c);
  float md = fmaxf(u, fminf(v, c));
  float s = 1.0f + ex2(mn - md) + ex2(mn - mx);
  return mn - lg2(s);
}

__global__ __launch_bounds__(128) void softdtw_dp_kernel(float* __restrict__ out) {
  const int b = blockIdx.x;
  const int t = threadIdx.x;
  const int lane = t & 31, w = t >> 5;

  __shared__ float sb1[2][4];
  __shared__ float sb2[2][4];
  if (t < 8) {
    (&sb1[0][0])[t] = BIGF;
    (&sb2[0][0])[t] = BIGF;
  }

  float v1[4], v2[4];
#pragma unroll
  for (int k = 0; k < 4; k++) { v1[k] = BIGF; v2[k] = BIGF; }

  const float* base = g_Ddiag + (size_t)b * (DPITCH * SEQ) + 4 * t;
  __syncthreads();

  // one-diagonal DP step (all 4 cells independent given neighbor values)
#define DP_STEP(P, G4)                                                        \
  {                                                                           \
    const int rs = (P) & 1;                                                   \
    float nb1 = __shfl_up_sync(0xffffffffu, v1[3], 1);                        \
    float nb2 = __shfl_up_sync(0xffffffffu, v2[3], 1);                        \
    if (lane == 0) {                                                          \
      nb1 = (w == 0) ? BIGF : sb1[rs][w - 1];                                 \
      nb2 = (w == 0) ? (((P) == 0) ? 0.0f : BIGF) : sb2[rs][w - 1];           \
    }                                                                         \
    const float gg0 = (G4).x, gg1 = (G4).y, gg2 = (G4).z, gg3 = (G4).w;       \
    float sm0 = softmin3s(nb2,   nb1,   v1[0]);                               \
    float sm1 = softmin3s(v2[0], v1[0], v1[1]);                               \
    float sm2 = softmin3s(v2[1], v1[1], v1[2]);                               \
    float sm3 = softmin3s(v2[2], v1[2], v1[3]);                               \
    unsigned pr = (unsigned)((P) - 4 * t);                                    \
    float n0 = (pr     < (unsigned)SEQ) ? fmaf(gg0, L2E, sm0) : BIGF;         \
    float n1 = (pr - 1 < (unsigned)SEQ) ? fmaf(gg1, L2E, sm1) : BIGF;         \
    float n2 = (pr - 2 < (unsigned)SEQ) ? fmaf(gg2, L2E, sm2) : BIGF;         \
    float n3 = (pr - 3 < (unsigned)SEQ) ? fmaf(gg3, L2E, sm3) : BIGF;         \
    v2[0] = v1[0]; v2[1] = v1[1]; v2[2] = v1[2]; v2[3] = v1[3];               \
    v1[0] = n0;    v1[1] = n1;    v1[2] = n2;    v1[3] = n3;                  \
    if (lane == 31) { sb1[rs ^ 1][w] = v1[3]; sb2[rs ^ 1][w] = v2[3]; }       \
    __syncthreads();                                                          \
  }

  // prefetch pipeline: groups of 8 diagonals
  float4 cur[8];
#pragma unroll
  for (int j = 0; j < 8; j++)
    cur[j] = *reinterpret_cast<const float4*>(base + (size_t)j * SEQ);

  for (int g = 0; g < 127; ++g) {
    float4 nxt[8];
#pragma unroll
    for (int j = 0; j < 8; j++)
      nxt[j] = *reinterpret_cast<const float4*>(base + (size_t)(8 * (g + 1) + j) * SEQ);
#pragma unroll
    for (int j = 0; j < 8; j++) {
      const int p = 8 * g + j;
      DP_STEP(p, cur[j]);
    }
#pragma unroll
    for (int j = 0; j < 8; j++) cur[j] = nxt[j];
  }
  // epilogue: p = 1016 .. 1022
#pragma unroll
  for (int j = 0; j < 7; j++) {
    const int p = 1016 + j;
    DP_STEP(p, cur[j]);
  }

  if (t == 127) out[b] = v1[3] * LN2;  // R[N, M], back to nat domain
#undef DP_STEP
}

// ---------------------------------------------------------------------------
extern "C" void kernel_launch(void* const* d_in, const int* in_sizes, int n_in,
                              void* d_out, int out_size) {
  const float* X = (const float*)d_in[0];
  const float* Y = (const float*)d_in[1];
  float* out = (float*)d_out;

  dim3 grid_g(SEQ / TI, SEQ / TJ, BATCH);
  gemm_diag_kernel<<<grid_g, 128>>>(X, Y);
  softdtw_dp_kernel<<<BATCH, 128>>>(out);
}